// round 1
// baseline (speedup 1.0000x reference)
#include <cuda_runtime.h>
#include <cstdint>

// ---------------- problem constants ----------------
#define B32   32
#define NN    325      // s1 (GRU sequence length after reshape)
#define TT    12       // s2 (attention length)
#define DD    128
#define G3    384      // 3*D gates
#define BATCH 384      // B32*TT  (GRU batch)
#define MTOT  124800   // BATCH*NN rows
#define HH    8
#define HD    16

// ---------------- scratch (device globals; no allocation allowed) ----------
__device__ float g_xw[(size_t)3 * MTOT * G3];  // 575 MB: input projections (incl. bih)
__device__ float g_ys[(size_t)3 * MTOT * DD];  // 192 MB: GRU outputs  [gru][i=b*12+t][j=n][d]
__device__ float g_ao[(size_t)MTOT * DD];      //  64 MB: attention out [b][n][t][d]

// ---------------- small helpers ----------------
__device__ __forceinline__ float sigmoidf_(float x) {
    return __fdividef(1.f, 1.f + __expf(-x));
}
__device__ __forceinline__ float tanhf_(float x) {
    return __fdividef(2.f, 1.f + __expf(-2.f * x)) - 1.f;
}

__device__ __forceinline__ void cp_async16(void* dst_smem, const void* src_gmem) {
    unsigned d = (unsigned)__cvta_generic_to_shared(dst_smem);
    asm volatile("cp.async.cg.shared.global [%0], [%1], 16;" :: "r"(d), "l"(src_gmem) : "memory");
}
__device__ __forceinline__ void cp_commit() {
    asm volatile("cp.async.commit_group;" ::: "memory");
}

// ========================================================================
// GEMM: C[M=124800, N] = A[M,128] @ W[N,128]^T + bias      (fp32)
// BM=64, BN=128, full K=128 in smem (k-major, padded strides).
// asel: 0 -> A = Aext, 1 -> A = g_ao
// cslot: >=0 -> C = g_xw + slot*MTOT*G3 (ldc=384), -1 -> C = Cext (ldc=N)
// ========================================================================
__global__ void __launch_bounds__(256)
gemm128(const float* __restrict__ Aext, int asel,
        const float* __restrict__ W, const float* __restrict__ bias,
        float* __restrict__ Cext, int cslot, int N)
{
    extern __shared__ float sm[];
    float* As = sm;               // [128][65]  k-major, pad stride 65
    float* Bs = sm + 128 * 65;    // [128][129] k-major, pad stride 129

    const float* A = asel ? g_ao : Aext;
    float* C = (cslot >= 0) ? (g_xw + (size_t)cslot * MTOT * G3) : Cext;

    int tid = threadIdx.x;
    int m0 = blockIdx.x * 64;
    int n0 = blockIdx.y * 128;

    // load A tile (64x128) transposed to k-major; coalesced global, conflict-free smem
    for (int u = tid; u < 64 * 128; u += 256) {
        int r = u >> 7, c = u & 127;
        As[c * 65 + r] = A[(size_t)(m0 + r) * 128 + c];
    }
    // load W tile (128 rows x 128) transposed to k-major
    for (int u = tid; u < 128 * 128; u += 256) {
        int g = u >> 7, c = u & 127;
        Bs[c * 129 + g] = W[(size_t)(n0 + g) * 128 + c];
    }
    __syncthreads();

    int nsub = tid & 15;   // n = nsub + 16*jj  (conflict-free B reads)
    int msub = tid >> 4;   // m = msub*4 + i

    float acc[4][8];
#pragma unroll
    for (int i = 0; i < 4; i++)
#pragma unroll
        for (int j = 0; j < 8; j++) acc[i][j] = 0.f;

#pragma unroll 4
    for (int k = 0; k < 128; k++) {
        float a[4], b[8];
#pragma unroll
        for (int i = 0; i < 4; i++) a[i] = As[k * 65 + msub * 4 + i];
#pragma unroll
        for (int j = 0; j < 8; j++) b[j] = Bs[k * 129 + nsub + 16 * j];
#pragma unroll
        for (int i = 0; i < 4; i++)
#pragma unroll
            for (int j = 0; j < 8; j++) acc[i][j] += a[i] * b[j];
    }

#pragma unroll
    for (int i = 0; i < 4; i++) {
        size_t rb = (size_t)(m0 + msub * 4 + i) * N;
#pragma unroll
        for (int j = 0; j < 8; j++) {
            int col = n0 + nsub + 16 * j;
            C[rb + col] = acc[i][j] + __ldg(&bias[col]);
        }
    }
}

// ========================================================================
// GRU scan. One CTA = (gru, block of 8 batches), 325 sequential steps.
// 384 threads: thread g owns gate g (0..127 r | 128..255 z | 256..383 n).
// smem: Whh (k-major, pad 385) + H[128][8] + xw double buffer (2x8x384).
// ========================================================================
__global__ void __launch_bounds__(384, 1)
gru_scan(const float* __restrict__ Whh_q, const float* __restrict__ Whh_k,
         const float* __restrict__ Whh_v,
         const float* __restrict__ bhh_q, const float* __restrict__ bhh_k,
         const float* __restrict__ bhh_v)
{
    extern __shared__ float sm[];
    float* Ws = sm;                  // 128*385 = 49280 floats
    float* Hs = sm + 49280;          // 128*8   = 1024 floats  [d][b]
    float* Xs = sm + 50304;          // 2*8*384 = 6144 floats  [stage][b][g]

    int gru = blockIdx.x / 48;
    int bb  = blockIdx.x % 48;
    int i0  = bb * 8;

    const float* Whh = (gru == 0) ? Whh_q : (gru == 1) ? Whh_k : Whh_v;
    const float* bhh = (gru == 0) ? bhh_q : (gru == 1) ? bhh_k : bhh_v;

    int g = threadIdx.x;

    // load Whh -> Ws[d*385 + g] (coalesced gmem, conflict-free smem)
    for (int idx = g; idx < G3 * DD; idx += 384)
        Ws[(idx & 127) * 385 + (idx >> 7)] = Whh[idx];
    for (int idx = g; idx < DD * 8; idx += 384) Hs[idx] = 0.f;

    float bhh_g = bhh[g];
    const size_t xwbase = (size_t)(gru * BATCH + i0) * NN * G3;  // + b*NN*G3 + j*G3

    // prefetch step 0 into stage 0
    {
#pragma unroll
        for (int w = 0; w < 2; w++) {
            int c = g + w * 384;           // 768 x 16B chunks
            int b = c / 96, q = c % 96;
            cp_async16(Xs + b * 384 + q * 4,
                       g_xw + xwbase + (size_t)b * (NN * G3) + q * 4);
        }
        cp_commit();
    }
    __syncthreads();

    int gate = g >> 7;       // 0=r 1=z 2=n
    int e    = g & 127;
    float xn[8], ghn[8];

    for (int j = 0; j < NN; j++) {
        int cur = j & 1;
        bool has_next = (j + 1 < NN);
        if (has_next) {
            float* dstb = Xs + ((j + 1) & 1) * 3072;
#pragma unroll
            for (int w = 0; w < 2; w++) {
                int c = g + w * 384;
                int b = c / 96, q = c % 96;
                cp_async16(dstb + b * 384 + q * 4,
                           g_xw + xwbase + (size_t)b * (NN * G3) + (size_t)(j + 1) * G3 + q * 4);
            }
            cp_commit();
        }

        // gh[g][b] = sum_d Whh[g][d] * h[d][b]
        float acc[8];
#pragma unroll
        for (int b = 0; b < 8; b++) acc[b] = 0.f;
        const float4* H4 = (const float4*)Hs;
#pragma unroll 8
        for (int d = 0; d < 128; d++) {
            float w = Ws[d * 385 + g];
            float4 ha = H4[2 * d];
            float4 hb = H4[2 * d + 1];
            acc[0] += w * ha.x; acc[1] += w * ha.y; acc[2] += w * ha.z; acc[3] += w * ha.w;
            acc[4] += w * hb.x; acc[5] += w * hb.y; acc[6] += w * hb.z; acc[7] += w * hb.w;
        }

        if (has_next) asm volatile("cp.async.wait_group 1;" ::: "memory");
        else          asm volatile("cp.async.wait_group 0;" ::: "memory");
        __syncthreads();

        float* Xc = Xs + cur * 3072;
        if (gate < 2) {
            // r/z: overwrite consumed xw slot with activated gate value
#pragma unroll
            for (int b = 0; b < 8; b++) {
                float pre = Xc[b * 384 + g] + acc[b] + bhh_g;
                Xc[b * 384 + g] = sigmoidf_(pre);
            }
        } else {
#pragma unroll
            for (int b = 0; b < 8; b++) {
                xn[b]  = Xc[b * 384 + g];
                ghn[b] = acc[b] + bhh_g;
            }
        }
        __syncthreads();

        if (gate == 2) {
            float* yout = g_ys + ((size_t)(gru * BATCH + i0) * NN + j) * DD + e;
#pragma unroll
            for (int b = 0; b < 8; b++) {
                float r  = Xc[b * 384 + e];
                float z  = Xc[b * 384 + 128 + e];
                float nn = tanhf_(xn[b] + r * ghn[b]);
                float hp = Hs[e * 8 + b];
                float hnew = (1.f - z) * nn + z * hp;
                Hs[e * 8 + b] = hnew;
                yout[(size_t)b * (NN * DD)] = hnew;
            }
        }
        __syncthreads();
    }
}

// ========================================================================
// Attention: one block per (b, n); 96 threads = 8 heads x 12 t.
// q/k/v row for head h at (b,n,t): g_ys[gru][(b*12+t)][n][h*16..].
// Bias head index = (5*b + n) mod 8  (exact replica of the scrambled
// reshape in the reference).
// ========================================================================
__global__ void __launch_bounds__(96)
attn_kernel(const float* __restrict__ rel)
{
    __shared__ float ks[TT * DD];
    __shared__ float vs[TT * DD];

    int b = blockIdx.x / NN;
    int n = blockIdx.x % NN;
    int tid = threadIdx.x;
    const size_t GS = (size_t)MTOT * DD;

    for (int u = tid; u < TT * DD / 4; u += 96) {
        int s = u >> 5, c4 = u & 31;
        size_t base = ((size_t)(b * TT + s) * NN + n) * DD + c4 * 4;
        ((float4*)ks)[u] = *(const float4*)(g_ys + GS + base);
        ((float4*)vs)[u] = *(const float4*)(g_ys + 2 * GS + base);
    }
    __syncthreads();

    int h = tid / TT, t = tid % TT;

    float q[HD];
    size_t qb = ((size_t)(b * TT + t) * NN + n) * DD + h * HD;
#pragma unroll
    for (int i = 0; i < 4; i++) ((float4*)q)[i] = *(const float4*)(g_ys + qb + i * 4);

    int hb = (5 * b + n) & 7;
    const float* rp = rel + hb * TT * TT + t * TT;

    float srow[TT];
#pragma unroll
    for (int s = 0; s < TT; s++) {
        float a = 0.f;
#pragma unroll
        for (int d = 0; d < HD; d++) a += q[d] * ks[s * DD + h * HD + d];
        srow[s] = a * 0.25f + __ldg(&rp[s]);
    }

    float m = srow[0];
#pragma unroll
    for (int s = 1; s < TT; s++) m = fmaxf(m, srow[s]);
    float sum = 0.f;
#pragma unroll
    for (int s = 0; s < TT; s++) { srow[s] = __expf(srow[s] - m); sum += srow[s]; }
    float inv = __fdividef(1.f, sum);

    float o[HD];
#pragma unroll
    for (int d = 0; d < HD; d++) o[d] = 0.f;
#pragma unroll
    for (int s = 0; s < TT; s++) {
        float p = srow[s] * inv;
#pragma unroll
        for (int d = 0; d < HD; d++) o[d] += p * vs[s * DD + h * HD + d];
    }

    size_t ob = ((size_t)(b * NN + n) * TT + t) * DD + h * HD;
#pragma unroll
    for (int i = 0; i < 4; i++) *(float4*)(g_ao + ob + i * 4) = ((float4*)o)[i];
}

// ========================================================================
extern "C" void kernel_launch(void* const* d_in, const int* in_sizes, int n_in,
                              void* d_out, int out_size)
{
    const float* query = (const float*)d_in[0];
    const float* key   = (const float*)d_in[1];
    const float* value = (const float*)d_in[2];
    const float* Wih_q = (const float*)d_in[3];
    const float* Whh_q = (const float*)d_in[4];
    const float* bih_q = (const float*)d_in[5];
    const float* bhh_q = (const float*)d_in[6];
    const float* Wih_k = (const float*)d_in[7];
    const float* Whh_k = (const float*)d_in[8];
    const float* bih_k = (const float*)d_in[9];
    const float* bhh_k = (const float*)d_in[10];
    const float* Wih_v = (const float*)d_in[11];
    const float* Whh_v = (const float*)d_in[12];
    const float* bih_v = (const float*)d_in[13];
    const float* bhh_v = (const float*)d_in[14];
    const float* rel   = (const float*)d_in[15];
    const float* Wout  = (const float*)d_in[16];
    const float* bout  = (const float*)d_in[17];

    const int gemm_smem = (128 * 65 + 128 * 129) * 4;   // 99,328 B
    const int scan_smem = (128 * 385 + 128 * 8 + 2 * 8 * 384) * 4; // 225,792 B
    cudaFuncSetAttribute(gemm128, cudaFuncAttributeMaxDynamicSharedMemorySize, gemm_smem);
    cudaFuncSetAttribute(gru_scan, cudaFuncAttributeMaxDynamicSharedMemorySize, scan_smem);

    // 1) input projections xw = X @ Wih^T + bih  (3 GRUs)
    gemm128<<<dim3(MTOT / 64, 3), 256, gemm_smem>>>(query, 0, Wih_q, bih_q, nullptr, 0, G3);
    gemm128<<<dim3(MTOT / 64, 3), 256, gemm_smem>>>(key,   0, Wih_k, bih_k, nullptr, 1, G3);
    gemm128<<<dim3(MTOT / 64, 3), 256, gemm_smem>>>(value, 0, Wih_v, bih_v, nullptr, 2, G3);

    // 2) sequential GRU scans (3 GRUs x 48 batch-blocks, independent)
    gru_scan<<<144, 384, scan_smem>>>(Whh_q, Whh_k, Whh_v, bhh_q, bhh_k, bhh_v);

    // 3) tiny attentions
    attn_kernel<<<B32 * NN, 96>>>(rel);

    // 4) output projection
    gemm128<<<dim3(MTOT / 64, 1), 256, gemm_smem>>>(nullptr, 1, Wout, bout,
                                                    (float*)d_out, -1, DD);
}

// round 2
// speedup vs baseline: 1.0200x; 1.0200x over previous
#include <cuda_runtime.h>
#include <cstdint>

// ---------------- problem constants ----------------
#define B32   32
#define NN    325      // s1 (GRU sequence length after reshape)
#define TT    12       // s2 (attention length)
#define DD    128
#define G3    384      // 3*D gates
#define BATCH 384      // B32*TT  (GRU batch)
#define MTOT  124800   // BATCH*NN rows
#define HH    8
#define HD    16

typedef unsigned long long u64;

// ---------------- scratch (device globals; no allocation allowed) ----------
__device__ float g_xw[(size_t)3 * MTOT * G3];  // input projections (incl. bih)
__device__ float g_ys[(size_t)3 * MTOT * DD];  // GRU outputs  [gru][i=b*12+t][j=n][d]
__device__ float g_ao[(size_t)MTOT * DD];      // attention out [b][n][t][d]

// ---------------- packed fp32x2 helpers (sm_100+) ----------------
__device__ __forceinline__ void fma2(u64& d, u64 a, u64 b) {
    asm("fma.rn.f32x2 %0, %1, %2, %0;" : "+l"(d) : "l"(a), "l"(b));
}
__device__ __forceinline__ u64 pk(float lo, float hi) {
    u64 r; asm("mov.b64 %0, {%1, %2};" : "=l"(r) : "f"(lo), "f"(hi)); return r;
}
__device__ __forceinline__ void upk(u64 v, float& lo, float& hi) {
    asm("mov.b64 {%0, %1}, %2;" : "=f"(lo), "=f"(hi) : "l"(v));
}

// ---------------- small helpers ----------------
__device__ __forceinline__ float sigmoidf_(float x) {
    return __fdividef(1.f, 1.f + __expf(-x));
}
__device__ __forceinline__ float tanhf_(float x) {
    return __fdividef(2.f, 1.f + __expf(-2.f * x)) - 1.f;
}

__device__ __forceinline__ void cp_async16(void* dst_smem, const void* src_gmem) {
    unsigned d = (unsigned)__cvta_generic_to_shared(dst_smem);
    asm volatile("cp.async.cg.shared.global [%0], [%1], 16;" :: "r"(d), "l"(src_gmem) : "memory");
}
__device__ __forceinline__ void cp_commit() {
    asm volatile("cp.async.commit_group;" ::: "memory");
}

// ========================================================================
// GEMM: C[M=124800, N] = A[M,128] @ W[N,128]^T + bias      (fp32, FFMA2)
// BM=64, BN=128, full K=128 in smem (k-major).
// Accumulators packed over M-pairs: a-pairs read as LDS.64 from k-major A.
// asel: 0 -> A = Aext, 1 -> A = g_ao
// cslot: >=0 -> C = g_xw + slot*MTOT*G3 (ldc=384), -1 -> C = Cext (ldc=N)
// ========================================================================
#define AST 66   // As stride (even -> 8B-aligned u64 reads)
#define BST 129

__global__ void __launch_bounds__(256)
gemm128(const float* __restrict__ Aext, int asel,
        const float* __restrict__ W, const float* __restrict__ bias,
        float* __restrict__ Cext, int cslot, int N)
{
    extern __shared__ float sm[];
    float* As = sm;                 // [128][AST]  k-major
    float* Bs = sm + 128 * AST;     // [128][BST]  k-major

    const float* A = asel ? g_ao : Aext;
    float* C = (cslot >= 0) ? (g_xw + (size_t)cslot * MTOT * G3) : Cext;

    int tid = threadIdx.x;
    int m0 = blockIdx.x * 64;
    int n0 = blockIdx.y * 128;

    // load A tile (64x128) transposed to k-major (coalesced gmem)
    for (int u = tid; u < 64 * 128; u += 256) {
        int r = u >> 7, c = u & 127;
        As[c * AST + r] = A[(size_t)(m0 + r) * 128 + c];
    }
    // load W tile (128 rows x 128) transposed to k-major
    for (int u = tid; u < 128 * 128; u += 256) {
        int g = u >> 7, c = u & 127;
        Bs[c * BST + g] = W[(size_t)(n0 + g) * 128 + c];
    }
    __syncthreads();

    int nsub = tid & 15;   // n = nsub + 16*j  (conflict-free B reads)
    int msub = tid >> 4;   // m = msub*4 + 2*ii + {0,1}

    u64 acc[2][8];
#pragma unroll
    for (int i = 0; i < 2; i++)
#pragma unroll
        for (int j = 0; j < 8; j++) acc[i][j] = 0ull;

#pragma unroll 4
    for (int k = 0; k < 128; k++) {
        // a-pairs: (m, m+1) adjacent in k-major As -> direct LDS.64
        const u64* Ak = (const u64*)(As + k * AST + msub * 4);
        u64 ap0 = Ak[0];
        u64 ap1 = Ak[1];
        float b[8];
#pragma unroll
        for (int j = 0; j < 8; j++) b[j] = Bs[k * BST + nsub + 16 * j];
#pragma unroll
        for (int j = 0; j < 8; j++) {
            u64 bd = pk(b[j], b[j]);
            fma2(acc[0][j], ap0, bd);
            fma2(acc[1][j], ap1, bd);
        }
    }

#pragma unroll
    for (int i = 0; i < 2; i++) {
        size_t r0 = (size_t)(m0 + msub * 4 + 2 * i) * N;
#pragma unroll
        for (int j = 0; j < 8; j++) {
            int col = n0 + nsub + 16 * j;
            float lo, hi;
            upk(acc[i][j], lo, hi);
            float bv = __ldg(&bias[col]);
            C[r0 + col] = lo + bv;
            C[r0 + N + col] = hi + bv;
        }
    }
}

// ========================================================================
// GRU scan. One CTA = (gru, block of 8 batches), 325 sequential steps.
// 384 threads: thread g owns gate g (0..127 r | 128..255 z | 256..383 n).
// Recurrent matvec packed over d-pairs: Whh stored [g][d] (stride 130),
// H stored [b][d] -> both FFMA2 operands are natural LDS.64 pairs, 0 packs.
// ========================================================================
#define WST 130
#define WS_FLOATS (G3 * WST)          // 49920
#define HS_OFF    WS_FLOATS
#define XS_OFF    (WS_FLOATS + 1024)

__global__ void __launch_bounds__(384, 1)
gru_scan(const float* __restrict__ Whh_q, const float* __restrict__ Whh_k,
         const float* __restrict__ Whh_v,
         const float* __restrict__ bhh_q, const float* __restrict__ bhh_k,
         const float* __restrict__ bhh_v)
{
    extern __shared__ float sm[];
    float* Ws = sm;             // [g][d] stride WST
    float* Hs = sm + HS_OFF;    // [b][d]: 8*128
    float* Xs = sm + XS_OFF;    // 2*8*384 double buffer [stage][b][g]

    int gru = blockIdx.x / 48;
    int bb  = blockIdx.x % 48;
    int i0  = bb * 8;

    const float* Whh = (gru == 0) ? Whh_q : (gru == 1) ? Whh_k : Whh_v;
    const float* bhh = (gru == 0) ? bhh_q : (gru == 1) ? bhh_k : bhh_v;

    int g = threadIdx.x;

    // Whh -> Ws[g*WST + d] (coalesced gmem; conflict-free smem: lanes write consecutive d)
    for (int idx = g; idx < G3 * DD; idx += 384)
        Ws[(idx >> 7) * WST + (idx & 127)] = Whh[idx];
    for (int idx = g; idx < DD * 8; idx += 384) Hs[idx] = 0.f;

    float bhh_g = bhh[g];
    const size_t xwbase = (size_t)(gru * BATCH + i0) * NN * G3;

    // prefetch step 0 into stage 0
    {
#pragma unroll
        for (int w = 0; w < 2; w++) {
            int c = g + w * 384;           // 768 x 16B chunks
            int b = c / 96, q = c % 96;
            cp_async16(Xs + b * 384 + q * 4,
                       g_xw + xwbase + (size_t)b * (NN * G3) + q * 4);
        }
        cp_commit();
    }
    __syncthreads();

    int gate = g >> 7;       // 0=r 1=z 2=n
    int e    = g & 127;
    float xn[8], ghn[8];

    const u64* Wg = (const u64*)(Ws + (size_t)g * WST);   // 64 d-pairs
    const u64* H2 = (const u64*)Hs;                       // [b*64 + dd]

    for (int j = 0; j < NN; j++) {
        int cur = j & 1;
        bool has_next = (j + 1 < NN);
        if (has_next) {
            float* dstb = Xs + ((j + 1) & 1) * 3072;
#pragma unroll
            for (int w = 0; w < 2; w++) {
                int c = g + w * 384;
                int b = c / 96, q = c % 96;
                cp_async16(dstb + b * 384 + q * 4,
                           g_xw + xwbase + (size_t)b * (NN * G3) + (size_t)(j + 1) * G3 + q * 4);
            }
            cp_commit();
        }

        // gh[g][b] = sum_d Whh[g][d] * h[b][d]   (packed over d-pairs)
        u64 acc2[8];
#pragma unroll
        for (int b = 0; b < 8; b++) acc2[b] = 0ull;
#pragma unroll 8
        for (int dd = 0; dd < 64; dd++) {
            u64 w2 = Wg[dd];
            fma2(acc2[0], w2, H2[dd]);
            fma2(acc2[1], w2, H2[64 + dd]);
            fma2(acc2[2], w2, H2[128 + dd]);
            fma2(acc2[3], w2, H2[192 + dd]);
            fma2(acc2[4], w2, H2[256 + dd]);
            fma2(acc2[5], w2, H2[320 + dd]);
            fma2(acc2[6], w2, H2[384 + dd]);
            fma2(acc2[7], w2, H2[448 + dd]);
        }
        float acc[8];
#pragma unroll
        for (int b = 0; b < 8; b++) {
            float lo, hi; upk(acc2[b], lo, hi);
            acc[b] = lo + hi;
        }

        if (has_next) asm volatile("cp.async.wait_group 1;" ::: "memory");
        else          asm volatile("cp.async.wait_group 0;" ::: "memory");
        __syncthreads();

        float* Xc = Xs + cur * 3072;
        if (gate < 2) {
            // r/z: overwrite consumed xw slot with activated gate value
#pragma unroll
            for (int b = 0; b < 8; b++) {
                float pre = Xc[b * 384 + g] + acc[b] + bhh_g;
                Xc[b * 384 + g] = sigmoidf_(pre);
            }
        } else {
#pragma unroll
            for (int b = 0; b < 8; b++) {
                xn[b]  = Xc[b * 384 + g];
                ghn[b] = acc[b] + bhh_g;
            }
        }
        __syncthreads();

        if (gate == 2) {
            float* yout = g_ys + ((size_t)(gru * BATCH + i0) * NN + j) * DD + e;
#pragma unroll
            for (int b = 0; b < 8; b++) {
                float r  = Xc[b * 384 + e];
                float z  = Xc[b * 384 + 128 + e];
                float nn = tanhf_(xn[b] + r * ghn[b]);
                float hp = Hs[b * 128 + e];
                float hnew = (1.f - z) * nn + z * hp;
                Hs[b * 128 + e] = hnew;
                yout[(size_t)b * (NN * DD)] = hnew;
            }
        }
        __syncthreads();
    }
}

// ========================================================================
// Attention: one block per (b, n); 96 threads = 8 heads x 12 t.
// Bias head index = (5*b + n) mod 8  (replica of scrambled reshape).
// ========================================================================
__global__ void __launch_bounds__(96)
attn_kernel(const float* __restrict__ rel)
{
    __shared__ float ks[TT * DD];
    __shared__ float vs[TT * DD];

    int b = blockIdx.x / NN;
    int n = blockIdx.x % NN;
    int tid = threadIdx.x;
    const size_t GS = (size_t)MTOT * DD;

    for (int u = tid; u < TT * DD / 4; u += 96) {
        int s = u >> 5, c4 = u & 31;
        size_t base = ((size_t)(b * TT + s) * NN + n) * DD + c4 * 4;
        ((float4*)ks)[u] = *(const float4*)(g_ys + GS + base);
        ((float4*)vs)[u] = *(const float4*)(g_ys + 2 * GS + base);
    }
    __syncthreads();

    int h = tid / TT, t = tid % TT;

    float q[HD];
    size_t qb = ((size_t)(b * TT + t) * NN + n) * DD + h * HD;
#pragma unroll
    for (int i = 0; i < 4; i++) ((float4*)q)[i] = *(const float4*)(g_ys + qb + i * 4);

    int hb = (5 * b + n) & 7;
    const float* rp = rel + hb * TT * TT + t * TT;

    float srow[TT];
#pragma unroll
    for (int s = 0; s < TT; s++) {
        float a = 0.f;
#pragma unroll
        for (int d = 0; d < HD; d++) a += q[d] * ks[s * DD + h * HD + d];
        srow[s] = a * 0.25f + __ldg(&rp[s]);
    }

    float m = srow[0];
#pragma unroll
    for (int s = 1; s < TT; s++) m = fmaxf(m, srow[s]);
    float sum = 0.f;
#pragma unroll
    for (int s = 0; s < TT; s++) { srow[s] = __expf(srow[s] - m); sum += srow[s]; }
    float inv = __fdividef(1.f, sum);

    float o[HD];
#pragma unroll
    for (int d = 0; d < HD; d++) o[d] = 0.f;
#pragma unroll
    for (int s = 0; s < TT; s++) {
        float p = srow[s] * inv;
#pragma unroll
        for (int d = 0; d < HD; d++) o[d] += p * vs[s * DD + h * HD + d];
    }

    size_t ob = ((size_t)(b * NN + n) * TT + t) * DD + h * HD;
#pragma unroll
    for (int i = 0; i < 4; i++) *(float4*)(g_ao + ob + i * 4) = ((float4*)o)[i];
}

// ========================================================================
extern "C" void kernel_launch(void* const* d_in, const int* in_sizes, int n_in,
                              void* d_out, int out_size)
{
    const float* query = (const float*)d_in[0];
    const float* key   = (const float*)d_in[1];
    const float* value = (const float*)d_in[2];
    const float* Wih_q = (const float*)d_in[3];
    const float* Whh_q = (const float*)d_in[4];
    const float* bih_q = (const float*)d_in[5];
    const float* bhh_q = (const float*)d_in[6];
    const float* Wih_k = (const float*)d_in[7];
    const float* Whh_k = (const float*)d_in[8];
    const float* bih_k = (const float*)d_in[9];
    const float* bhh_k = (const float*)d_in[10];
    const float* Wih_v = (const float*)d_in[11];
    const float* Whh_v = (const float*)d_in[12];
    const float* bih_v = (const float*)d_in[13];
    const float* bhh_v = (const float*)d_in[14];
    const float* rel   = (const float*)d_in[15];
    const float* Wout  = (const float*)d_in[16];
    const float* bout  = (const float*)d_in[17];

    const int gemm_smem = (128 * AST + 128 * BST) * 4;                 //  99,840 B
    const int scan_smem = (WS_FLOATS + 1024 + 2 * 8 * 384) * 4;        // 228,352 B
    cudaFuncSetAttribute(gemm128, cudaFuncAttributeMaxDynamicSharedMemorySize, gemm_smem);
    cudaFuncSetAttribute(gru_scan, cudaFuncAttributeMaxDynamicSharedMemorySize, scan_smem);

    // 1) input projections xw = X @ Wih^T + bih  (3 GRUs)
    gemm128<<<dim3(MTOT / 64, 3), 256, gemm_smem>>>(query, 0, Wih_q, bih_q, nullptr, 0, G3);
    gemm128<<<dim3(MTOT / 64, 3), 256, gemm_smem>>>(key,   0, Wih_k, bih_k, nullptr, 1, G3);
    gemm128<<<dim3(MTOT / 64, 3), 256, gemm_smem>>>(value, 0, Wih_v, bih_v, nullptr, 2, G3);

    // 2) sequential GRU scans (3 GRUs x 48 batch-blocks, independent)
    gru_scan<<<144, 384, scan_smem>>>(Whh_q, Whh_k, Whh_v, bhh_q, bhh_k, bhh_v);

    // 3) tiny attentions
    attn_kernel<<<B32 * NN, 96>>>(rel);

    // 4) output projection
    gemm128<<<dim3(MTOT / 64, 1), 256, gemm_smem>>>(nullptr, 1, Wout, bout,
                                                    (float*)d_out, -1, DD);
}